// round 14
// baseline (speedup 1.0000x reference)
#include <cuda_runtime.h>

#define N_NODES 50000
#define N_EDGES 800000
#define F_IN 128
#define HID 160
#define OUT_C 128
#define NGR 64
#define OUT_DIM 10
#define NB 444            // 3 resident CTAs per SM (148 SMs)
#define NT 512            // threads per block
#define TT (NB * NT)      // 227328 total threads  >= 200000 hop tasks
#define NCHUNK 98         // ceil(50000/512) scan chunks

// ---------------- static scratch (no allocations allowed) ----------------
__device__ int    d_indeg[N_NODES];
__device__ int    d_ptr[N_NODES + 1];
__device__ int    d_cursor[N_NODES];
__device__ float  d_dinv[N_NODES];
__device__ int2   d_edge[N_EDGES];       // {src, norm as float bits}
__device__ float4 d_H0[N_NODES * 4];     // 16 floats per node = 64B row
__device__ float4 d_H1[N_NODES * 4];
__device__ float  d_c5[N_NODES];
__device__ float  d_c10[N_NODES];
__device__ float  d_P3[HID * OUT_DIM];
__device__ float  d_P2[HID * OUT_DIM];
__device__ float  d_R [F_IN * OUT_DIM];
__device__ float  d_g1[OUT_DIM];
__device__ float  d_g2[OUT_DIM];
__device__ float  d_g3[OUT_DIM];
__device__ float  d_pooled[NGR * OUT_DIM];
__device__ int    d_counts[NGR];
__device__ int    d_bsum[NCHUNK];

// ---------------- software grid barrier ----------------
// Release side publishes via __threadfence (writes -> L2). Acquire side is
// only __threadfence_block: all cross-SM-written data after a barrier is read
// either via __ldcg (L2) or is first-touch / self-written in L1 (audited).
// No CCTL.IVALL -> CSR metadata stays L1-resident across all hops.
__device__ unsigned g_count = 0;
__device__ unsigned g_phase = 0;

__device__ __forceinline__ void gsync() {
    __threadfence();                 // release: publish writes to L2
    __syncthreads();
    if (threadIdx.x == 0) {
        unsigned gen = *(volatile unsigned*)&g_phase;
        if (atomicAdd(&g_count, 1u) == NB - 1) {
            *(volatile unsigned*)&g_count = 0;
            __threadfence();
            atomicAdd(&g_phase, 1u);
        } else {
            while (*(volatile unsigned*)&g_phase == gen) __nanosleep(32);
        }
    }
    __syncthreads();
    __threadfence_block();           // compiler/intra-CTA ordering only (no L1 flush)
}

__device__ __forceinline__ void fma4(float4& a, float4 v, float w) {
    a.x += w * v.x; a.y += w * v.y; a.z += w * v.z; a.w += w * v.w;
}

__global__ __launch_bounds__(NT, 3)
void k_mega(const float* __restrict__ x, const int* __restrict__ ei,
            const int* __restrict__ batch,
            const float* __restrict__ W1, const float* __restrict__ b1,
            const float* __restrict__ W2, const float* __restrict__ b2,
            const float* __restrict__ W3, const float* __restrict__ b3,
            const float* __restrict__ fc_w, const float* __restrict__ fc_b,
            float* __restrict__ out) {
    const int tid  = threadIdx.x;
    const int gt   = blockIdx.x * NT + tid;
    const int lane = tid & 31, wid = tid >> 5;

    __shared__ int   sW[16];
    __shared__ int   sOff[NCHUNK];
    __shared__ float sR[F_IN * OUT_DIM];     // 5 KB
    __shared__ float sp[NGR * OUT_DIM];      // 2.5 KB
    __shared__ int   sc[NGR];
    __shared__ float sg1[OUT_DIM], sg2[OUT_DIM], sg3[OUT_DIM];

    // ---- P0: zero deg/pool; params1: P3 = W3 @ fc_w, g3 = b3 @ fc_w ----
    for (int i = gt; i < N_NODES; i += TT) d_indeg[i] = 0;
    for (int i = gt; i < NGR * OUT_DIM; i += TT) d_pooled[i] = 0.f;
    for (int i = gt; i < NGR; i += TT) d_counts[i] = 0;
    for (int t = gt; t < HID * OUT_DIM + OUT_DIM; t += TT) {
        if (t < HID * OUT_DIM) {
            int i = t / OUT_DIM, c = t % OUT_DIM;
            float a = 0.f;
            for (int k = 0; k < OUT_C; k++) a += W3[i * OUT_C + k] * fc_w[k * OUT_DIM + c];
            d_P3[t] = a;
        } else {
            int c = t - HID * OUT_DIM;
            float a = 0.f;
            for (int k = 0; k < OUT_C; k++) a += b3[k] * fc_w[k * OUT_DIM + c];
            d_g3[c] = a;
        }
    }
    gsync();

    // ---- P1: degree histogram (int4); params2: P2 = W2 @ P3, g2 = b2 @ P3 ----
    for (int e4 = gt; e4 < N_EDGES / 4; e4 += TT) {
        int4 d = *(const int4*)&ei[N_EDGES + e4 * 4];
        atomicAdd(&d_indeg[d.x], 1);
        atomicAdd(&d_indeg[d.y], 1);
        atomicAdd(&d_indeg[d.z], 1);
        atomicAdd(&d_indeg[d.w], 1);
    }
    for (int t = gt; t < HID * OUT_DIM + OUT_DIM; t += TT) {
        if (t < HID * OUT_DIM) {
            int i = t / OUT_DIM, c = t % OUT_DIM;
            float a = 0.f;
            for (int k = 0; k < HID; k++) a += W2[i * HID + k] * d_P3[k * OUT_DIM + c];
            d_P2[t] = a;
        } else {
            int c = t - HID * OUT_DIM;
            float a = 0.f;
            for (int k = 0; k < HID; k++) a += b2[k] * d_P3[k * OUT_DIM + c];
            d_g2[c] = a;
        }
    }
    gsync();

    // ---- P2: per-chunk exclusive scan (blocks 0..97); params3: R = W1 @ P2, g1 ----
    if (blockIdx.x < NCHUNK) {
        int i = blockIdx.x * NT + tid;
        int v = (i < N_NODES) ? __ldcg(&d_indeg[i]) : 0;
        int incl = v;
        #pragma unroll
        for (int off = 1; off < 32; off <<= 1) {
            int n = __shfl_up_sync(0xffffffffu, incl, off);
            if (lane >= off) incl += n;
        }
        if (lane == 31) sW[wid] = incl;
        __syncthreads();
        if (wid == 0) {
            int s = (lane < 16) ? sW[lane] : 0;
            #pragma unroll
            for (int off = 1; off < 16; off <<= 1) {
                int n = __shfl_up_sync(0xffffffffu, s, off);
                if (lane >= off) s += n;
            }
            if (lane < 16) sW[lane] = s;
        }
        __syncthreads();
        int wexcl = wid ? sW[wid - 1] : 0;
        if (i < N_NODES) d_ptr[i] = wexcl + incl - v;  // exclusive within chunk
        if (tid == 0) d_bsum[blockIdx.x] = sW[15];
    }
    for (int t = gt; t < F_IN * OUT_DIM + OUT_DIM; t += TT) {
        if (t < F_IN * OUT_DIM) {
            int i = t / OUT_DIM, c = t % OUT_DIM;
            float a = 0.f;
            for (int k = 0; k < HID; k++) a += W1[i * HID + k] * d_P2[k * OUT_DIM + c];
            d_R[t] = a;
        } else {
            int c = t - F_IN * OUT_DIM;
            float a = 0.f;
            for (int k = 0; k < HID; k++) a += b1[k] * d_P2[k * OUT_DIM + c];
            d_g1[c] = a;
        }
    }
    gsync();

    // ---- P3: scan fixup + cursor + dinv; init H0 = [X@R (10), ones@10, 0...] ----
    if (tid == 0) {
        int run = 0;
        for (int b = 0; b < NCHUNK; b++) { sOff[b] = run; run += __ldcg(&d_bsum[b]); }
    }
    __syncthreads();
    for (int i = gt; i < N_NODES; i += TT) {
        int p = __ldcg(&d_ptr[i]) + sOff[i >> 9];
        d_ptr[i] = p;
        d_cursor[i] = p;
        d_dinv[i] = rsqrtf((float)(__ldcg(&d_indeg[i]) + 1));
    }
    if (gt == 0) d_ptr[N_NODES] = N_EDGES;
    for (int i = tid; i < F_IN * OUT_DIM; i += NT) sR[i] = __ldcg(&d_R[i]);
    __syncthreads();
    // 4 threads per node; thread q computes channels 4q..4q+3 (single pass)
    if (gt < N_NODES * 4) {
        int t = gt;
        int node = t >> 2, q = t & 3;
        float4 a = make_float4(0.f, 0.f, 0.f, 0.f);
        if (q < 2) {                 // channels 0-3 / 4-7
            const float4* xr = (const float4*)(x + node * F_IN);
            int cb = q * 4;
            float av[4] = {0, 0, 0, 0};
            #pragma unroll 4
            for (int k = 0; k < F_IN / 4; k++) {
                float4 xv = xr[k];
                const float* r0 = &sR[(4 * k) * OUT_DIM + cb];
                #pragma unroll
                for (int j = 0; j < 4; j++)
                    av[j] += xv.x * r0[j] + xv.y * r0[OUT_DIM + j]
                           + xv.z * r0[2 * OUT_DIM + j] + xv.w * r0[3 * OUT_DIM + j];
            }
            a = make_float4(av[0], av[1], av[2], av[3]);
        } else if (q == 2) {         // channels 8,9 + ones at channel 10
            const float4* xr = (const float4*)(x + node * F_IN);
            float a0 = 0.f, a1 = 0.f;
            #pragma unroll 4
            for (int k = 0; k < F_IN / 4; k++) {
                float4 xv = xr[k];
                const float* r0 = &sR[(4 * k) * OUT_DIM + 8];
                a0 += xv.x * r0[0] + xv.y * r0[OUT_DIM] + xv.z * r0[2 * OUT_DIM] + xv.w * r0[3 * OUT_DIM];
                a1 += xv.x * r0[1] + xv.y * r0[OUT_DIM + 1] + xv.z * r0[2 * OUT_DIM + 1] + xv.w * r0[3 * OUT_DIM + 1];
            }
            a = make_float4(a0, a1, 1.0f, 0.f);
        }                            // q==3: zeros
        d_H0[t] = a;
    }
    gsync();

    // ---- P4: scatter edges into dst-CSR ----
    for (int e = gt; e < N_EDGES; e += TT) {
        int s = ei[e];
        int d = ei[N_EDGES + e];
        int p = atomicAdd(&d_cursor[d], 1);
        d_edge[p] = make_int2(s, __float_as_int(__ldg(&d_dinv[s]) * __ldg(&d_dinv[d])));
    }
    gsync();

    // ---- P5..P19: 15 hops; gathers via __ldcg (L2), meta/ptr/dinv L1-resident,
    //      self row = own-thread previous write -> plain L1 hit ----
    for (int hop = 1; hop <= 15; hop++) {
        const float4* __restrict__ h = (hop & 1) ? d_H0 : d_H1;
        float4* __restrict__ o       = (hop & 1) ? d_H1 : d_H0;
        int snap = (hop == 5) ? 1 : (hop == 10) ? 2 : 0;
        if (gt < N_NODES * 4) {
            int t = gt;
            int node = t >> 2, q = t & 3;
            int e = d_ptr[node], end = d_ptr[node + 1];
            float4 a = make_float4(0.f, 0.f, 0.f, 0.f);
            float4 b = make_float4(0.f, 0.f, 0.f, 0.f);
            if ((e & 1) && e < end) {                  // align to even for int4 meta
                int2 m = d_edge[e];
                fma4(a, __ldcg(&h[(m.x << 2) | q]), __int_as_float(m.y));
                e++;
            }
            // 4 gathers in flight per iteration
            for (; e + 3 < end; e += 4) {
                int4 m01 = *(const int4*)&d_edge[e];
                int4 m23 = *(const int4*)&d_edge[e + 2];
                float4 v0 = __ldcg(&h[(m01.x << 2) | q]);
                float4 v1 = __ldcg(&h[(m01.z << 2) | q]);
                float4 v2 = __ldcg(&h[(m23.x << 2) | q]);
                float4 v3 = __ldcg(&h[(m23.z << 2) | q]);
                fma4(a, v0, __int_as_float(m01.y));
                fma4(b, v1, __int_as_float(m01.w));
                fma4(a, v2, __int_as_float(m23.y));
                fma4(b, v3, __int_as_float(m23.w));
            }
            if (e + 1 < end) {                         // 2-edge tail
                int4 m01 = *(const int4*)&d_edge[e];
                float4 v0 = __ldcg(&h[(m01.x << 2) | q]);
                float4 v1 = __ldcg(&h[(m01.z << 2) | q]);
                fma4(a, v0, __int_as_float(m01.y));
                fma4(b, v1, __int_as_float(m01.w));
                e += 2;
            }
            if (e < end) {                             // 1-edge tail
                int2 m = d_edge[e];
                fma4(a, __ldcg(&h[(m.x << 2) | q]), __int_as_float(m.y));
            }
            float dn = d_dinv[node];
            fma4(a, h[(node << 2) | q], dn * dn);      // self row: own-L1 fresh
            a.x += b.x; a.y += b.y; a.z += b.z; a.w += b.w;
            if (snap && q == 2) {                      // q==2 holds ch 8..11; a.z == ch 10
                if (snap == 1) d_c5[node] = a.z;
                else           d_c10[node] = a.z;
            }
            o[t] = a;
        }
        gsync();
    }

    // ---- P20: pooling (block-shared accumulate, then global atomics) ----
    for (int i = tid; i < NGR * OUT_DIM; i += NT) sp[i] = 0.f;
    if (tid < NGR) sc[tid] = 0;
    if (tid < OUT_DIM) { sg1[tid] = __ldcg(&d_g1[tid]); sg2[tid] = __ldcg(&d_g2[tid]); sg3[tid] = __ldcg(&d_g3[tid]); }
    __syncthreads();
    for (int n = gt; n < N_NODES; n += TT) {
        int bg = batch[n];
        atomicAdd(&sc[bg], 1);
        float a10 = __ldcg(&d_c10[n]), a5 = __ldcg(&d_c5[n]);
        float4 r0 = __ldcg(&d_H1[n * 4]);
        float4 r1 = __ldcg(&d_H1[n * 4 + 1]);
        float4 r2 = __ldcg(&d_H1[n * 4 + 2]);   // final state after hop 15
        float hv[10] = {r0.x, r0.y, r0.z, r0.w, r1.x, r1.y, r1.z, r1.w, r2.x, r2.y};
        #pragma unroll
        for (int c = 0; c < OUT_DIM; c++) {
            float z = hv[c] + a10 * sg1[c] + a5 * sg2[c] + sg3[c];
            atomicAdd(&sp[bg * OUT_DIM + c], z);
        }
    }
    __syncthreads();
    for (int i = tid; i < NGR * OUT_DIM; i += NT)
        if (sp[i] != 0.f) atomicAdd(&d_pooled[i], sp[i]);
    if (tid < NGR && sc[tid]) atomicAdd(&d_counts[tid], sc[tid]);
    gsync();

    // ---- P21: mean, +fc_b, log_softmax (block 0) ----
    if (blockIdx.x == 0 && tid < NGR) {
        float cnt = (float)__ldcg(&d_counts[tid]);
        if (cnt < 1.f) cnt = 1.f;
        float l[OUT_DIM];
        float m = -1e30f;
        #pragma unroll
        for (int c = 0; c < OUT_DIM; c++) {
            l[c] = __ldcg(&d_pooled[tid * OUT_DIM + c]) / cnt + fc_b[c];
            m = fmaxf(m, l[c]);
        }
        float s = 0.f;
        #pragma unroll
        for (int c = 0; c < OUT_DIM; c++) s += expf(l[c] - m);
        float lse = m + logf(s);
        #pragma unroll
        for (int c = 0; c < OUT_DIM; c++) out[tid * OUT_DIM + c] = l[c] - lse;
    }
}

// ---------------- launch ----------------
extern "C" void kernel_launch(void* const* d_in, const int* in_sizes, int n_in,
                              void* d_out, int out_size) {
    (void)in_sizes; (void)n_in; (void)out_size;
    const float* x     = (const float*)d_in[0];
    const int*   ei    = (const int*)d_in[1];     // int32 (JAX x64 disabled)
    const int*   batch = (const int*)d_in[2];     // int32
    const float* W1    = (const float*)d_in[3];
    const float* b1    = (const float*)d_in[4];
    const float* W2    = (const float*)d_in[5];
    const float* b2    = (const float*)d_in[6];
    const float* W3    = (const float*)d_in[7];
    const float* b3    = (const float*)d_in[8];
    const float* fc_w  = (const float*)d_in[9];
    const float* fc_b  = (const float*)d_in[10];
    float* out = (float*)d_out;

    k_mega<<<NB, NT>>>(x, ei, batch, W1, b1, W2, b2, W3, b3, fc_w, fc_b, out);
}

// round 15
// speedup vs baseline: 1.0723x; 1.0723x over previous
#include <cuda_runtime.h>

#define N_NODES 50000
#define N_EDGES 800000
#define F_IN 128
#define HID 160
#define OUT_C 128
#define NGR 64
#define OUT_DIM 10
#define NB 444            // 3 resident CTAs per SM (148 SMs)
#define NT 512            // threads per block
#define TT (NB * NT)      // 227328 total threads  >= 200000 hop tasks
#define NCHUNK 98         // ceil(50000/512) scan chunks

// ---------------- static scratch (no allocations allowed) ----------------
__device__ int    d_indeg[N_NODES];
__device__ int    d_ptr[N_NODES + 1];
__device__ int    d_cursor[N_NODES];
__device__ float  d_dinv[N_NODES];
__device__ int2   d_edge[N_EDGES];         // {src, norm as float bits}
__device__ float4 d_H[16][N_NODES * 4];    // 16 hop buffers: no line is ever re-read stale
__device__ float  d_c5[N_NODES];
__device__ float  d_c10[N_NODES];
__device__ float  d_P3[HID * OUT_DIM];
__device__ float  d_P2[HID * OUT_DIM];
__device__ float  d_R [F_IN * OUT_DIM];
__device__ float  d_g1[OUT_DIM];
__device__ float  d_g2[OUT_DIM];
__device__ float  d_g3[OUT_DIM];
__device__ float  d_pooled[NGR * OUT_DIM];
__device__ int    d_counts[NGR];
__device__ int    d_bsum[NCHUNK];

// ---------------- software grid barrier ----------------
// Release: __threadfence publishes writes to L2. Acquire: __threadfence_block
// only (no CCTL.IVALL / L1 flush). Safe because each hop reads a buffer no SM
// has ever read before (16 distinct buffers), CSR metadata is write-once, and
// atomically-updated accumulators are read via __ldcg.
__device__ unsigned g_count = 0;
__device__ unsigned g_phase = 0;

__device__ __forceinline__ void gsync() {
    __threadfence();                 // release: publish writes to L2
    __syncthreads();
    if (threadIdx.x == 0) {
        unsigned gen = *(volatile unsigned*)&g_phase;
        if (atomicAdd(&g_count, 1u) == NB - 1) {
            *(volatile unsigned*)&g_count = 0;
            __threadfence();
            atomicAdd(&g_phase, 1u);
        } else {
            while (*(volatile unsigned*)&g_phase == gen) __nanosleep(32);
        }
    }
    __syncthreads();
    __threadfence_block();           // compiler/intra-CTA ordering only (no L1 flush)
}

__device__ __forceinline__ void fma4(float4& a, float4 v, float w) {
    a.x += w * v.x; a.y += w * v.y; a.z += w * v.z; a.w += w * v.w;
}

__global__ __launch_bounds__(NT, 3)
void k_mega(const float* __restrict__ x, const int* __restrict__ ei,
            const int* __restrict__ batch,
            const float* __restrict__ W1, const float* __restrict__ b1,
            const float* __restrict__ W2, const float* __restrict__ b2,
            const float* __restrict__ W3, const float* __restrict__ b3,
            const float* __restrict__ fc_w, const float* __restrict__ fc_b,
            float* __restrict__ out) {
    const int tid  = threadIdx.x;
    const int gt   = blockIdx.x * NT + tid;
    const int lane = tid & 31, wid = tid >> 5;

    __shared__ int   sW[16];
    __shared__ int   sOff[NCHUNK];
    __shared__ float sR[F_IN * OUT_DIM];     // 5 KB
    __shared__ float sp[NGR * OUT_DIM];      // 2.5 KB
    __shared__ int   sc[NGR];
    __shared__ float sg1[OUT_DIM], sg2[OUT_DIM], sg3[OUT_DIM];

    // ---- P0: zero deg/pool; params1: P3 = W3 @ fc_w, g3 = b3 @ fc_w ----
    for (int i = gt; i < N_NODES; i += TT) d_indeg[i] = 0;
    for (int i = gt; i < NGR * OUT_DIM; i += TT) d_pooled[i] = 0.f;
    for (int i = gt; i < NGR; i += TT) d_counts[i] = 0;
    for (int t = gt; t < HID * OUT_DIM + OUT_DIM; t += TT) {
        if (t < HID * OUT_DIM) {
            int i = t / OUT_DIM, c = t % OUT_DIM;
            float a = 0.f;
            for (int k = 0; k < OUT_C; k++) a += W3[i * OUT_C + k] * fc_w[k * OUT_DIM + c];
            d_P3[t] = a;
        } else {
            int c = t - HID * OUT_DIM;
            float a = 0.f;
            for (int k = 0; k < OUT_C; k++) a += b3[k] * fc_w[k * OUT_DIM + c];
            d_g3[c] = a;
        }
    }
    gsync();

    // ---- P1: degree histogram (int4); params2: P2 = W2 @ P3, g2 = b2 @ P3 ----
    for (int e4 = gt; e4 < N_EDGES / 4; e4 += TT) {
        int4 d = *(const int4*)&ei[N_EDGES + e4 * 4];
        atomicAdd(&d_indeg[d.x], 1);
        atomicAdd(&d_indeg[d.y], 1);
        atomicAdd(&d_indeg[d.z], 1);
        atomicAdd(&d_indeg[d.w], 1);
    }
    for (int t = gt; t < HID * OUT_DIM + OUT_DIM; t += TT) {
        if (t < HID * OUT_DIM) {
            int i = t / OUT_DIM, c = t % OUT_DIM;
            float a = 0.f;
            for (int k = 0; k < HID; k++) a += W2[i * HID + k] * d_P3[k * OUT_DIM + c];
            d_P2[t] = a;
        } else {
            int c = t - HID * OUT_DIM;
            float a = 0.f;
            for (int k = 0; k < HID; k++) a += b2[k] * d_P3[k * OUT_DIM + c];
            d_g2[c] = a;
        }
    }
    gsync();

    // ---- P2: per-chunk exclusive scan (blocks 0..97); params3: R = W1 @ P2, g1 ----
    if (blockIdx.x < NCHUNK) {
        int i = blockIdx.x * NT + tid;
        // d_indeg: zeroed by own store at P0 (same i=gt mapping) then atomically
        // updated in L2 -> must bypass potentially write-allocated L1 line
        int v = (i < N_NODES) ? __ldcg(&d_indeg[i]) : 0;
        int incl = v;
        #pragma unroll
        for (int off = 1; off < 32; off <<= 1) {
            int n = __shfl_up_sync(0xffffffffu, incl, off);
            if (lane >= off) incl += n;
        }
        if (lane == 31) sW[wid] = incl;
        __syncthreads();
        if (wid == 0) {
            int s = (lane < 16) ? sW[lane] : 0;
            #pragma unroll
            for (int off = 1; off < 16; off <<= 1) {
                int n = __shfl_up_sync(0xffffffffu, s, off);
                if (lane >= off) s += n;
            }
            if (lane < 16) sW[lane] = s;
        }
        __syncthreads();
        int wexcl = wid ? sW[wid - 1] : 0;
        if (i < N_NODES) d_ptr[i] = wexcl + incl - v;  // exclusive within chunk
        if (tid == 0) d_bsum[blockIdx.x] = sW[15];
    }
    for (int t = gt; t < F_IN * OUT_DIM + OUT_DIM; t += TT) {
        if (t < F_IN * OUT_DIM) {
            int i = t / OUT_DIM, c = t % OUT_DIM;
            float a = 0.f;
            for (int k = 0; k < HID; k++) a += W1[i * HID + k] * d_P2[k * OUT_DIM + c];
            d_R[t] = a;
        } else {
            int c = t - F_IN * OUT_DIM;
            float a = 0.f;
            for (int k = 0; k < HID; k++) a += b1[k] * d_P2[k * OUT_DIM + c];
            d_g1[c] = a;
        }
    }
    gsync();

    // ---- P3: scan fixup + cursor + dinv; init H[0] = [X@R (10), ones@10, 0...] ----
    if (tid == 0) {
        int run = 0;
        for (int b = 0; b < NCHUNK; b++) { sOff[b] = run; run += d_bsum[b]; }  // first-touch/own
    }
    __syncthreads();
    for (int i = gt; i < N_NODES; i += TT) {
        int p = d_ptr[i] + sOff[i >> 9];             // own-thread store at P2 -> fresh
        d_ptr[i] = p;
        d_cursor[i] = p;
        d_dinv[i] = rsqrtf((float)(__ldcg(&d_indeg[i]) + 1));
    }
    if (gt == 0) d_ptr[N_NODES] = N_EDGES;
    for (int i = tid; i < F_IN * OUT_DIM; i += NT) sR[i] = d_R[i];   // first touch
    __syncthreads();
    // 4 threads per node; thread q computes channels 4q..4q+3 (single pass)
    if (gt < N_NODES * 4) {
        int t = gt;
        int node = t >> 2, q = t & 3;
        float4 a = make_float4(0.f, 0.f, 0.f, 0.f);
        if (q < 2) {                 // channels 0-3 / 4-7
            const float4* xr = (const float4*)(x + node * F_IN);
            int cb = q * 4;
            float av[4] = {0, 0, 0, 0};
            #pragma unroll 4
            for (int k = 0; k < F_IN / 4; k++) {
                float4 xv = xr[k];
                const float* r0 = &sR[(4 * k) * OUT_DIM + cb];
                #pragma unroll
                for (int j = 0; j < 4; j++)
                    av[j] += xv.x * r0[j] + xv.y * r0[OUT_DIM + j]
                           + xv.z * r0[2 * OUT_DIM + j] + xv.w * r0[3 * OUT_DIM + j];
            }
            a = make_float4(av[0], av[1], av[2], av[3]);
        } else if (q == 2) {         // channels 8,9 + ones at channel 10
            const float4* xr = (const float4*)(x + node * F_IN);
            float a0 = 0.f, a1 = 0.f;
            #pragma unroll 4
            for (int k = 0; k < F_IN / 4; k++) {
                float4 xv = xr[k];
                const float* r0 = &sR[(4 * k) * OUT_DIM + 8];
                a0 += xv.x * r0[0] + xv.y * r0[OUT_DIM] + xv.z * r0[2 * OUT_DIM] + xv.w * r0[3 * OUT_DIM];
                a1 += xv.x * r0[1] + xv.y * r0[OUT_DIM + 1] + xv.z * r0[2 * OUT_DIM + 1] + xv.w * r0[3 * OUT_DIM + 1];
            }
            a = make_float4(a0, a1, 1.0f, 0.f);
        }                            // q==3: zeros
        d_H[0][t] = a;
    }
    gsync();

    // ---- P4: scatter edges into dst-CSR ----
    for (int e = gt; e < N_EDGES; e += TT) {
        int s = ei[e];
        int d = ei[N_EDGES + e];
        int p = atomicAdd(&d_cursor[d], 1);
        d_edge[p] = make_int2(s, __float_as_int(__ldg(&d_dinv[s]) * __ldg(&d_dinv[d])));
    }
    gsync();

    // ---- P5..P19: 15 hops; hop k reads d_H[k-1] (never read before by any SM ->
    //      first touch, no staleness), writes d_H[k]. Meta stays L1-resident. ----
    for (int hop = 1; hop <= 15; hop++) {
        const float4* __restrict__ h = d_H[hop - 1];
        float4* __restrict__ o       = d_H[hop];
        int snap = (hop == 5) ? 1 : (hop == 10) ? 2 : 0;
        if (gt < N_NODES * 4) {
            int t = gt;
            int node = t >> 2, q = t & 3;
            int e = d_ptr[node], end = d_ptr[node + 1];
            float4 a = make_float4(0.f, 0.f, 0.f, 0.f);
            float4 b = make_float4(0.f, 0.f, 0.f, 0.f);
            if ((e & 1) && e < end) {                  // align to even for int4 meta
                int2 m = d_edge[e];
                fma4(a, h[(m.x << 2) | q], __int_as_float(m.y));
                e++;
            }
            // 4 gathers in flight per iteration
            for (; e + 3 < end; e += 4) {
                int4 m01 = *(const int4*)&d_edge[e];
                int4 m23 = *(const int4*)&d_edge[e + 2];
                float4 v0 = h[(m01.x << 2) | q];
                float4 v1 = h[(m01.z << 2) | q];
                float4 v2 = h[(m23.x << 2) | q];
                float4 v3 = h[(m23.z << 2) | q];
                fma4(a, v0, __int_as_float(m01.y));
                fma4(b, v1, __int_as_float(m01.w));
                fma4(a, v2, __int_as_float(m23.y));
                fma4(b, v3, __int_as_float(m23.w));
            }
            if (e + 1 < end) {                         // 2-edge tail
                int4 m01 = *(const int4*)&d_edge[e];
                float4 v0 = h[(m01.x << 2) | q];
                float4 v1 = h[(m01.z << 2) | q];
                fma4(a, v0, __int_as_float(m01.y));
                fma4(b, v1, __int_as_float(m01.w));
                e += 2;
            }
            if (e < end) {                             // 1-edge tail
                int2 m = d_edge[e];
                fma4(a, h[(m.x << 2) | q], __int_as_float(m.y));
            }
            float dn = d_dinv[node];
            fma4(a, h[(node << 2) | q], dn * dn);      // self row
            a.x += b.x; a.y += b.y; a.z += b.z; a.w += b.w;
            if (snap && q == 2) {                      // q==2 holds ch 8..11; a.z == ch 10
                if (snap == 1) d_c5[node] = a.z;
                else           d_c10[node] = a.z;
            }
            o[t] = a;
        }
        gsync();
    }

    // ---- P20: pooling (block-shared accumulate, then global atomics) ----
    for (int i = tid; i < NGR * OUT_DIM; i += NT) sp[i] = 0.f;
    if (tid < NGR) sc[tid] = 0;
    if (tid < OUT_DIM) { sg1[tid] = d_g1[tid]; sg2[tid] = d_g2[tid]; sg3[tid] = d_g3[tid]; }
    __syncthreads();
    for (int n = gt; n < N_NODES; n += TT) {
        int bg = batch[n];
        atomicAdd(&sc[bg], 1);
        float a10 = d_c10[n], a5 = d_c5[n];        // first touch by this SM
        float4 r0 = d_H[15][n * 4];
        float4 r1 = d_H[15][n * 4 + 1];
        float4 r2 = d_H[15][n * 4 + 2];            // d_H[15]: first read here
        float hv[10] = {r0.x, r0.y, r0.z, r0.w, r1.x, r1.y, r1.z, r1.w, r2.x, r2.y};
        #pragma unroll
        for (int c = 0; c < OUT_DIM; c++) {
            float z = hv[c] + a10 * sg1[c] + a5 * sg2[c] + sg3[c];
            atomicAdd(&sp[bg * OUT_DIM + c], z);
        }
    }
    __syncthreads();
    for (int i = tid; i < NGR * OUT_DIM; i += NT)
        if (sp[i] != 0.f) atomicAdd(&d_pooled[i], sp[i]);
    if (tid < NGR && sc[tid]) atomicAdd(&d_counts[tid], sc[tid]);
    gsync();

    // ---- P21: mean, +fc_b, log_softmax (block 0) ----
    // d_pooled/d_counts were atomically updated in L2 after this block's own
    // zero-stores -> must read via __ldcg
    if (blockIdx.x == 0 && tid < NGR) {
        float cnt = (float)__ldcg(&d_counts[tid]);
        if (cnt < 1.f) cnt = 1.f;
        float l[OUT_DIM];
        float m = -1e30f;
        #pragma unroll
        for (int c = 0; c < OUT_DIM; c++) {
            l[c] = __ldcg(&d_pooled[tid * OUT_DIM + c]) / cnt + fc_b[c];
            m = fmaxf(m, l[c]);
        }
        float s = 0.f;
        #pragma unroll
        for (int c = 0; c < OUT_DIM; c++) s += expf(l[c] - m);
        float lse = m + logf(s);
        #pragma unroll
        for (int c = 0; c < OUT_DIM; c++) out[tid * OUT_DIM + c] = l[c] - lse;
    }
}

// ---------------- launch ----------------
extern "C" void kernel_launch(void* const* d_in, const int* in_sizes, int n_in,
                              void* d_out, int out_size) {
    (void)in_sizes; (void)n_in; (void)out_size;
    const float* x     = (const float*)d_in[0];
    const int*   ei    = (const int*)d_in[1];     // int32 (JAX x64 disabled)
    const int*   batch = (const int*)d_in[2];     // int32
    const float* W1    = (const float*)d_in[3];
    const float* b1    = (const float*)d_in[4];
    const float* W2    = (const float*)d_in[5];
    const float* b2    = (const float*)d_in[6];
    const float* W3    = (const float*)d_in[7];
    const float* b3    = (const float*)d_in[8];
    const float* fc_w  = (const float*)d_in[9];
    const float* fc_b  = (const float*)d_in[10];
    float* out = (float*)d_out;

    k_mega<<<NB, NT>>>(x, ei, batch, W1, b1, W2, b2, W3, b3, fc_w, fc_b, out);
}

// round 17
// speedup vs baseline: 1.3896x; 1.2959x over previous
#include <cuda_runtime.h>

#define N_NODES 50000
#define N_EDGES 800000
#define F_IN 128
#define HID 160
#define OUT_C 128
#define NGR 64
#define OUT_DIM 10
#define NB 444            // 3 resident CTAs per SM (148 SMs)
#define NT 512            // threads per block
#define TT (NB * NT)
#define CH 480            // hop tasks per block (32-aligned); 444*480 >= 200000
#define NTASK (N_NODES * 4)
#define NCHUNK 98         // ceil(50000/512) scan chunks

// ---------------- static scratch (no allocations allowed) ----------------
__device__ int    d_indeg[N_NODES];        // zeroed by phase D for next replay
__device__ int    d_ptr[N_NODES + 1];
__device__ int    d_cursor[N_NODES];
__device__ float  d_dinv[N_NODES];
__device__ int    d_esrc[N_EDGES];         // CSR src index only (weight-free G-iteration)
__device__ float4 d_H[15][N_NODES * 4];    // hop buffers 0..14 (hop15 consumed in regs)
__device__ float  d_P3[HID * OUT_DIM];
__device__ float  d_P2[HID * OUT_DIM];
__device__ float  d_R [F_IN * OUT_DIM];
__device__ float  d_g1[OUT_DIM];
__device__ float  d_g2[OUT_DIM];
__device__ float  d_g3[OUT_DIM];
__device__ float  d_pooled[NGR * OUT_DIM]; // zeroed by phase D
__device__ int    d_counts[NGR];           // zeroed by phase D
__device__ int    d_bsum[NCHUNK];

// ---------------- software grid barrier (release to L2, no L1 flush) ----------------
__device__ unsigned g_count = 0;
__device__ unsigned g_phase = 0;

__device__ __forceinline__ void gsync() {
    __threadfence();                 // release: publish writes to L2
    __syncthreads();
    if (threadIdx.x == 0) {
        unsigned gen = *(volatile unsigned*)&g_phase;
        if (atomicAdd(&g_count, 1u) == NB - 1) {
            *(volatile unsigned*)&g_count = 0;
            __threadfence();
            atomicAdd(&g_phase, 1u);
        } else {
            while (*(volatile unsigned*)&g_phase == gen) __nanosleep(32);
        }
    }
    __syncthreads();
    __threadfence_block();           // no CCTL.IVALL: L1 keeps CSR metadata across hops
}

__device__ __forceinline__ void add4(float4& a, float4 v) {
    a.x += v.x; a.y += v.y; a.z += v.z; a.w += v.w;
}

__global__ __launch_bounds__(NT, 3)
void k_mega(const float* __restrict__ x, const int* __restrict__ ei,
            const int* __restrict__ batch,
            const float* __restrict__ W1, const float* __restrict__ b1,
            const float* __restrict__ W2, const float* __restrict__ b2,
            const float* __restrict__ W3, const float* __restrict__ b3,
            const float* __restrict__ fc_w, const float* __restrict__ fc_b,
            float* __restrict__ out) {
    const int tid  = threadIdx.x;
    const int gt   = blockIdx.x * NT + tid;
    const int lane = tid & 31, wid = tid >> 5;
    const int task = blockIdx.x * CH + tid;          // balanced hop/init mapping
    const bool tv  = (tid < CH) && (task < NTASK);
    const int node = task >> 2, q = task & 3;

    __shared__ int   sW[16];
    __shared__ int   sOff[NCHUNK];
    __shared__ float sR[F_IN * OUT_DIM];     // 5 KB
    __shared__ float sp[NGR * OUT_DIM];      // 2.5 KB
    __shared__ int   sc[NGR];
    __shared__ float sg1[OUT_DIM], sg2[OUT_DIM], sg3[OUT_DIM];

    // ---- Phase A: degree histogram (d_indeg is zero: static init / prev-replay D);
    //      params1: P3 = W3 @ fc_w, g3 = b3 @ fc_w ----
    for (int e4 = gt; e4 < N_EDGES / 4; e4 += TT) {
        int4 d = *(const int4*)&ei[N_EDGES + e4 * 4];
        atomicAdd(&d_indeg[d.x], 1);
        atomicAdd(&d_indeg[d.y], 1);
        atomicAdd(&d_indeg[d.z], 1);
        atomicAdd(&d_indeg[d.w], 1);
    }
    for (int t = gt; t < HID * OUT_DIM + OUT_DIM; t += TT) {
        if (t < HID * OUT_DIM) {
            int i = t / OUT_DIM, c = t % OUT_DIM;
            float a = 0.f;
            for (int k = 0; k < OUT_C; k++) a += W3[i * OUT_C + k] * fc_w[k * OUT_DIM + c];
            d_P3[t] = a;
        } else {
            int c = t - HID * OUT_DIM;
            float a = 0.f;
            for (int k = 0; k < OUT_C; k++) a += b3[k] * fc_w[k * OUT_DIM + c];
            d_g3[c] = a;
        }
    }
    gsync();

    // ---- Phase B: per-chunk exclusive scan; params2: P2 = W2 @ P3, g2 ----
    if (blockIdx.x < NCHUNK) {
        int i = blockIdx.x * NT + tid;
        int v = (i < N_NODES) ? __ldcg(&d_indeg[i]) : 0;   // atomics live in L2
        int incl = v;
        #pragma unroll
        for (int off = 1; off < 32; off <<= 1) {
            int n = __shfl_up_sync(0xffffffffu, incl, off);
            if (lane >= off) incl += n;
        }
        if (lane == 31) sW[wid] = incl;
        __syncthreads();
        if (wid == 0) {
            int s = (lane < 16) ? sW[lane] : 0;
            #pragma unroll
            for (int off = 1; off < 16; off <<= 1) {
                int n = __shfl_up_sync(0xffffffffu, s, off);
                if (lane >= off) s += n;
            }
            if (lane < 16) sW[lane] = s;
        }
        __syncthreads();
        int wexcl = wid ? sW[wid - 1] : 0;
        if (i < N_NODES) d_ptr[i] = wexcl + incl - v;
        if (tid == 0) d_bsum[blockIdx.x] = sW[15];
    }
    for (int t = gt; t < HID * OUT_DIM + OUT_DIM; t += TT) {
        if (t < HID * OUT_DIM) {
            int i = t / OUT_DIM, c = t % OUT_DIM;
            float a = 0.f;
            for (int k = 0; k < HID; k++) a += W2[i * HID + k] * d_P3[k * OUT_DIM + c];
            d_P2[t] = a;
        } else {
            int c = t - HID * OUT_DIM;
            float a = 0.f;
            for (int k = 0; k < HID; k++) a += b2[k] * d_P3[k * OUT_DIM + c];
            d_g2[c] = a;
        }
    }
    gsync();

    // ---- Phase C: scan fixup + cursor + dinv; params3: R = W1 @ P2, g1 ----
    if (tid == 0) {
        int run = 0;
        for (int b = 0; b < NCHUNK; b++) { sOff[b] = run; run += __ldcg(&d_bsum[b]); }
    }
    __syncthreads();
    for (int i = gt; i < N_NODES; i += TT) {
        int p = d_ptr[i] + sOff[i >> 9];        // own-thread store at B -> fresh
        d_ptr[i] = p;
        d_cursor[i] = p;
        d_dinv[i] = rsqrtf((float)(__ldcg(&d_indeg[i]) + 1));
    }
    if (gt == 0) d_ptr[N_NODES] = N_EDGES;
    for (int t = gt; t < F_IN * OUT_DIM + OUT_DIM; t += TT) {
        if (t < F_IN * OUT_DIM) {
            int i = t / OUT_DIM, c = t % OUT_DIM;
            float a = 0.f;
            for (int k = 0; k < HID; k++) a += W1[i * HID + k] * d_P2[k * OUT_DIM + c];
            d_R[t] = a;
        } else {
            int c = t - F_IN * OUT_DIM;
            float a = 0.f;
            for (int k = 0; k < HID; k++) a += b1[k] * d_P2[k * OUT_DIM + c];
            d_g1[c] = a;
        }
    }
    gsync();

    // ---- Phase D: scatter edges (src only); init G0 = dinv * [X@R, 1, 0...];
    //      zero accumulators for this run / d_indeg for next replay ----
    for (int i = gt; i < NGR * OUT_DIM; i += TT) d_pooled[i] = 0.f;
    for (int i = gt; i < NGR; i += TT) d_counts[i] = 0;
    for (int i = gt; i < N_NODES; i += TT) d_indeg[i] = 0;
    for (int e = gt; e < N_EDGES; e += TT) {
        int s = ei[e];
        int d = ei[N_EDGES + e];
        int p = atomicAdd(&d_cursor[d], 1);
        d_esrc[p] = s;
    }
    for (int i = tid; i < F_IN * OUT_DIM; i += NT) sR[i] = __ldcg(&d_R[i]);
    __syncthreads();
    if (tv) {
        float dn = d_dinv[node];
        float4 a = make_float4(0.f, 0.f, 0.f, 0.f);
        if (q < 2) {                 // channels 0-3 / 4-7
            const float4* xr = (const float4*)(x + node * F_IN);
            int cb = q * 4;
            float av[4] = {0, 0, 0, 0};
            #pragma unroll 4
            for (int k = 0; k < F_IN / 4; k++) {
                float4 xv = xr[k];
                const float* r0 = &sR[(4 * k) * OUT_DIM + cb];
                #pragma unroll
                for (int j = 0; j < 4; j++)
                    av[j] += xv.x * r0[j] + xv.y * r0[OUT_DIM + j]
                           + xv.z * r0[2 * OUT_DIM + j] + xv.w * r0[3 * OUT_DIM + j];
            }
            a = make_float4(dn * av[0], dn * av[1], dn * av[2], dn * av[3]);
        } else if (q == 2) {         // channels 8,9 + ones at channel 10
            const float4* xr = (const float4*)(x + node * F_IN);
            float a0 = 0.f, a1 = 0.f;
            #pragma unroll 4
            for (int k = 0; k < F_IN / 4; k++) {
                float4 xv = xr[k];
                const float* r0 = &sR[(4 * k) * OUT_DIM + 8];
                a0 += xv.x * r0[0] + xv.y * r0[OUT_DIM] + xv.z * r0[2 * OUT_DIM] + xv.w * r0[3 * OUT_DIM];
                a1 += xv.x * r0[1] + xv.y * r0[OUT_DIM + 1] + xv.z * r0[2 * OUT_DIM + 1] + xv.w * r0[3 * OUT_DIM + 1];
            }
            a = make_float4(dn * a0, dn * a1, dn, 0.f);
        }                            // q==3: zeros (stay zero forever)
        d_H[0][task] = a;
    }
    gsync();

    // ---- Hops 1..15 on G: G'[d] = dinv[d]^2 * (sum_e G[src_e] + G[d]).
    //      Weight-free: meta = int4 of 4 src indices. Hop 15 fuses pooling. ----
    float snap5 = 0.f, snap10 = 0.f;           // q==2 lane keeps ch10 snapshots in regs
    for (int hop = 1; hop <= 15; hop++) {
        const float4* __restrict__ g = d_H[hop - 1];
        if (hop == 15) {                       // prep pooling shared state
            for (int i = tid; i < NGR * OUT_DIM; i += NT) sp[i] = 0.f;
            if (tid < NGR) sc[tid] = 0;
            if (tid < OUT_DIM) { sg1[tid] = d_g1[tid]; sg2[tid] = d_g2[tid]; sg3[tid] = d_g3[tid]; }
            __syncthreads();
        }
        if (tv) {
            int e = d_ptr[node], end = d_ptr[node + 1];
            float4 a = g[task];                // self term (own-written last hop)
            float4 b = make_float4(0.f, 0.f, 0.f, 0.f);
            int pre = (4 - (e & 3)) & 3;       // peel to 16B alignment
            if (pre > end - e) pre = end - e;
            for (int i = 0; i < pre; i++, e++) add4(a, g[(d_esrc[e] << 2) | q]);
            for (; e + 3 < end; e += 4) {      // 4 gathers in flight, 1 meta load
                int4 s4 = *(const int4*)&d_esrc[e];
                float4 v0 = g[(s4.x << 2) | q];
                float4 v1 = g[(s4.y << 2) | q];
                float4 v2 = g[(s4.z << 2) | q];
                float4 v3 = g[(s4.w << 2) | q];
                add4(a, v0); add4(b, v1); add4(a, v2); add4(b, v3);
            }
            for (; e < end; e++) add4(a, g[(d_esrc[e] << 2) | q]);
            float dn = d_dinv[node];
            float w = dn * dn;
            float4 r;
            r.x = w * (a.x + b.x); r.y = w * (a.y + b.y);
            r.z = w * (a.z + b.z); r.w = w * (a.w + b.w);
            if (q == 2) {
                if (hop == 5)  snap5  = r.z;   // G5 channel 10
                if (hop == 10) snap10 = r.z;   // G10 channel 10
            }
            if (hop < 15) {
                d_H[hop][task] = r;
            } else {
                // ---- fused pooling: H = G/dinv; corrections via reg snapshots ----
                float rd = 1.0f / dn;
                float s10 = __shfl_sync(0xffffffffu, snap10, 2, 4);  // from quad lane q=2
                float s5  = __shfl_sync(0xffffffffu, snap5,  2, 4);
                float h10 = s10 * rd, h5 = s5 * rd;
                int bg = batch[node];
                int cb = q * 4;
                float rr[4] = {r.x, r.y, r.z, r.w};
                #pragma unroll
                for (int j = 0; j < 4; j++) {
                    int c = cb + j;
                    if (c < OUT_DIM) {
                        float z = rr[j] * rd + h10 * sg1[c] + h5 * sg2[c] + sg3[c];
                        atomicAdd(&sp[bg * OUT_DIM + c], z);
                    }
                }
                if (q == 3) atomicAdd(&sc[bg], 1);
            }
        }
        if (hop == 15) {                       // flush block partials to global
            __syncthreads();
            for (int i = tid; i < NGR * OUT_DIM; i += NT)
                if (sp[i] != 0.f) atomicAdd(&d_pooled[i], sp[i]);
            if (tid < NGR && sc[tid]) atomicAdd(&d_counts[tid], sc[tid]);
        }
        gsync();
    }

    // ---- Final: mean, +fc_b, log_softmax (block 0) ----
    if (blockIdx.x == 0 && tid < NGR) {
        float cnt = (float)__ldcg(&d_counts[tid]);
        if (cnt < 1.f) cnt = 1.f;
        float l[OUT_DIM];
        float m = -1e30f;
        #pragma unroll
        for (int c = 0; c < OUT_DIM; c++) {
            l[c] = __ldcg(&d_pooled[tid * OUT_DIM + c]) / cnt + fc_b[c];
            m = fmaxf(m, l[c]);
        }
        float s = 0.f;
        #pragma unroll
        for (int c = 0; c < OUT_DIM; c++) s += expf(l[c] - m);
        float lse = m + logf(s);
        #pragma unroll
        for (int c = 0; c < OUT_DIM; c++) out[tid * OUT_DIM + c] = l[c] - lse;
    }
}

// ---------------- launch ----------------
extern "C" void kernel_launch(void* const* d_in, const int* in_sizes, int n_in,
                              void* d_out, int out_size) {
    (void)in_sizes; (void)n_in; (void)out_size;
    const float* x     = (const float*)d_in[0];
    const int*   ei    = (const int*)d_in[1];     // int32 (JAX x64 disabled)
    const int*   batch = (const int*)d_in[2];     // int32
    const float* W1    = (const float*)d_in[3];
    const float* b1    = (const float*)d_in[4];
    const float* W2    = (const float*)d_in[5];
    const float* b2    = (const float*)d_in[6];
    const float* W3    = (const float*)d_in[7];
    const float* b3    = (const float*)d_in[8];
    const float* fc_w  = (const float*)d_in[9];
    const float* fc_b  = (const float*)d_in[10];
    float* out = (float*)d_out;

    k_mega<<<NB, NT>>>(x, ei, batch, W1, b1, W2, b2, W3, b3, fc_w, fc_b, out);
}